// round 10
// baseline (speedup 1.0000x reference)
#include <cuda_runtime.h>
#include <cuda_fp16.h>

#define MAXN 50176
#define SLOT 128
#define LOG2E 1.4426950408889634f

// Scratch (__device__ globals; no allocation allowed)
__device__ __align__(256) __half2 g_h2h[MAXN * 32];  // layer-2 features fp16 packed
__device__ __align__(16) float2 g_sx1[MAXN];         // packed (s1, x)
__device__ __align__(16) float2 g_sh3[MAXN];         // packed (s3, h3)
__device__ __align__(16) float2 g_dz1[MAXN];         // layer-1 (den, num); INVARIANT: zero at entry (zero-init; K3 resets)
__device__ __align__(16) float2 g_dz3[MAXN];         // layer-3 (den, num); initialized by K4 epilogue each call
__device__ float g_d1[MAXN];
__device__ float g_s2[MAXN], g_d2[MAXN];
__device__ float g_d3[MAXN];
__device__ int g_cursor[MAXN];       // INVARIANT: zero at entry (zero-init; K6 resets)
__device__ int g_csr[MAXN * SLOT];   // fixed-stride CSR

__device__ __forceinline__ float leaky(float v) { return v > 0.f ? v : 0.2f * v; }

__device__ __forceinline__ void red_add_v2(float2* p, float a, float b) {
    asm volatile("red.global.add.v2.f32 [%0], {%1, %2};" :: "l"(p), "f"(a), "f"(b) : "memory");
}

// ======= K1: node prep — layer-1 rank-1 scalars =======
__global__ void prep(const float* __restrict__ x, const float* __restrict__ W1,
                     const float* __restrict__ as1, const float* __restrict__ ad1, int N) {
    __shared__ float cs_sh, cd_sh;
    if (threadIdx.x == 0) {
        float cs = 0.f, cd = 0.f;
#pragma unroll
        for (int j = 0; j < 64; j++) { cs += W1[j] * as1[j]; cd += W1[j] * ad1[j]; }
        cs_sh = cs; cd_sh = cd;
    }
    __syncthreads();
    int i = blockIdx.x * blockDim.x + threadIdx.x;
    if (i >= N) return;
    float xv = x[i];
    g_sx1[i] = make_float2(xv * cs_sh, xv);
    g_d1[i] = xv * cd_sh;
}

// ======= K2: edge pass 1 — CSR scatter + layer-1 REDG aggregation =======
__global__ void edge1(const int* __restrict__ src, const int* __restrict__ dst, int E) {
    int t = blockIdx.x * blockDim.x + threadIdx.x;
    int e0 = t * 4;
    if (e0 + 3 < E) {
        int4 s4 = ((const int4*)src)[t];
        int4 d4 = ((const int4*)dst)[t];
#pragma unroll
        for (int q = 0; q < 4; q++) {
            int s = (q == 0) ? s4.x : (q == 1) ? s4.y : (q == 2) ? s4.z : s4.w;
            int d = (q == 0) ? d4.x : (q == 1) ? d4.y : (q == 2) ? d4.z : d4.w;
            int r = atomicAdd(&g_cursor[d], 1);
            g_csr[d * SLOT + r] = s;
            float2 tv = g_sx1[s];
            float ex = exp2f(leaky(tv.x + g_d1[d]) * LOG2E);
            red_add_v2(&g_dz1[d], ex, ex * tv.y);
        }
    } else if (e0 < E) {
        for (int e = e0; e < E; e++) {
            int s = src[e], d = dst[e];
            int r = atomicAdd(&g_cursor[d], 1);
            g_csr[d * SLOT + r] = s;
            float2 tv = g_sx1[s];
            float ex = exp2f(leaky(tv.x + g_d1[d]) * LOG2E);
            red_add_v2(&g_dz1[d], ex, ex * tv.y);
        }
    }
}

// ======= K3: layer-1 finalize + layer-2 transform (warp per node) =======
__global__ void node2(const float* __restrict__ W1, const float* __restrict__ b1,
                      const float* __restrict__ W2,
                      const float* __restrict__ as2, const float* __restrict__ ad2, int N) {
    int node = (blockIdx.x * blockDim.x + threadIdx.x) >> 5;
    int lane = threadIdx.x & 31;
    if (node >= N) return;
    float2 self = g_sx1[node];
    float dn = g_d1[node];
    float2 dz;
    float z;
    if (lane == 0) {
        dz = g_dz1[node];
        g_dz1[node] = make_float2(0.f, 0.f);   // restore invariant
        float exs = exp2f(leaky(self.x + dn) * LOG2E);
        z = (dz.y + exs * self.y) / (dz.x + exs);
    }
    z = __shfl_sync(0xffffffffu, z, 0);

    float v0 = fmaxf(z * W1[lane] + b1[lane], 0.f);
    float v1 = fmaxf(z * W1[lane + 32] + b1[lane + 32], 0.f);
    float o0 = 0.f, o1 = 0.f;
#pragma unroll
    for (int k = 0; k < 64; k++) {
        float vk = __shfl_sync(0xffffffffu, (k < 32) ? v0 : v1, k & 31);
        float2 w = ((const float2*)W2)[k * 32 + lane];
        o0 += vk * w.x;
        o1 += vk * w.y;
    }
    g_h2h[node * 32 + lane] = __floats2half2_rn(o0, o1);
    float2 a_s = ((const float2*)as2)[lane];
    float2 a_d = ((const float2*)ad2)[lane];
    float ps = o0 * a_s.x + o1 * a_s.y;
    float pd = o0 * a_d.x + o1 * a_d.y;
#pragma unroll
    for (int o = 16; o; o >>= 1) {
        ps += __shfl_down_sync(0xffffffffu, ps, o);
        pd += __shfl_down_sync(0xffffffffu, pd, o);
    }
    if (lane == 0) { g_s2[node] = ps; g_d2[node] = pd; }
}

// ======= K4: layer-2 wide GAT + layer-3 projection; inits dz3 with self-loop =======
__global__ void gat_l2(const float* __restrict__ b2, const float* __restrict__ W3,
                       const float* __restrict__ as3, const float* __restrict__ ad3, int N) {
    int node = (blockIdx.x * blockDim.x + threadIdx.x) >> 5;
    int lane = threadIdx.x & 31;
    if (node >= N) return;
    int off = node * SLOT;
    int deg = g_cursor[node];
    float dn = g_d2[node];

    float exs = exp2f(leaky(g_s2[node] + dn) * LOG2E);
    float2 hself = __half22float2(g_h2h[node * 32 + lane]);
    float a0 = exs * hself.x;
    float a1 = exs * hself.y;
    float dsum = 0.f;
    for (int r = 0; r < deg; r += 32) {
        int j = r + lane;
        int sv = 0;
        float exv = 0.f;
        if (j < deg) {
            sv = g_csr[off + j];
            exv = exp2f(leaky(g_s2[sv] + dn) * LOG2E);
        }
        dsum += exv;
        int cnt = min(32, deg - r);
        if (cnt == 32) {
#pragma unroll 8
            for (int k = 0; k < 32; k++) {
                int sj = __shfl_sync(0xffffffffu, sv, k);
                float exj = __shfl_sync(0xffffffffu, exv, k);
                float2 hv = __half22float2(g_h2h[sj * 32 + lane]);
                a0 += exj * hv.x;
                a1 += exj * hv.y;
            }
        } else {
            for (int k = 0; k < cnt; k++) {
                int sj = __shfl_sync(0xffffffffu, sv, k);
                float exj = __shfl_sync(0xffffffffu, exv, k);
                float2 hv = __half22float2(g_h2h[sj * 32 + lane]);
                a0 += exj * hv.x;
                a1 += exj * hv.y;
            }
        }
    }
#pragma unroll
    for (int o = 16; o; o >>= 1) dsum += __shfl_xor_sync(0xffffffffu, dsum, o);
    float inv = 1.f / (exs + dsum);
    float2 bb = ((const float2*)b2)[lane];
    float2 w3 = ((const float2*)W3)[lane];
    float x30 = fmaxf(a0 * inv + bb.x, 0.f);
    float x31 = fmaxf(a1 * inv + bb.y, 0.f);
    float p = x30 * w3.x + x31 * w3.y;
#pragma unroll
    for (int o = 16; o; o >>= 1) p += __shfl_down_sync(0xffffffffu, p, o);
    if (lane == 0) {
        float s3 = p * as3[0];
        float d3 = p * ad3[0];
        g_sh3[node] = make_float2(s3, p);
        g_d3[node] = d3;
        float ex3 = exp2f(leaky(s3 + d3) * LOG2E);
        g_dz3[node] = make_float2(ex3, ex3 * p);   // self-loop init (ordered before K5 by kernel boundary)
    }
}

// ======= K5: edge pass 2 — layer-3 REDG aggregation =======
__global__ void edge3(const int* __restrict__ src, const int* __restrict__ dst, int E) {
    int t = blockIdx.x * blockDim.x + threadIdx.x;
    int e0 = t * 4;
    if (e0 + 3 < E) {
        int4 s4 = ((const int4*)src)[t];
        int4 d4 = ((const int4*)dst)[t];
#pragma unroll
        for (int q = 0; q < 4; q++) {
            int s = (q == 0) ? s4.x : (q == 1) ? s4.y : (q == 2) ? s4.z : s4.w;
            int d = (q == 0) ? d4.x : (q == 1) ? d4.y : (q == 2) ? d4.z : d4.w;
            float2 tv = g_sh3[s];
            float ex = exp2f(leaky(tv.x + g_d3[d]) * LOG2E);
            red_add_v2(&g_dz3[d], ex, ex * tv.y);
        }
    } else if (e0 < E) {
        for (int e = e0; e < E; e++) {
            int s = src[e], d = dst[e];
            float2 tv = g_sh3[s];
            float ex = exp2f(leaky(tv.x + g_d3[d]) * LOG2E);
            red_add_v2(&g_dz3[d], ex, ex * tv.y);
        }
    }
}

// ======= K6: finalize output; reset cursor invariant =======
__global__ void fin(const float* __restrict__ b3, float* __restrict__ out, int N) {
    int i = blockIdx.x * blockDim.x + threadIdx.x;
    if (i >= N) return;
    float2 dz = g_dz3[i];
    out[i] = dz.y / dz.x + b3[0];
    g_cursor[i] = 0;   // restore invariant for next call
}

extern "C" void kernel_launch(void* const* d_in, const int* in_sizes, int n_in,
                              void* d_out, int out_size) {
    const float* x   = (const float*)d_in[0];
    const int*   ei  = (const int*)d_in[1];
    const float* W1  = (const float*)d_in[3];
    const float* as1 = (const float*)d_in[4];
    const float* ad1 = (const float*)d_in[5];
    const float* b1  = (const float*)d_in[6];
    const float* W2  = (const float*)d_in[7];
    const float* as2 = (const float*)d_in[8];
    const float* ad2 = (const float*)d_in[9];
    const float* b2  = (const float*)d_in[10];
    const float* W3  = (const float*)d_in[11];
    const float* as3 = (const float*)d_in[12];
    const float* ad3 = (const float*)d_in[13];
    const float* b3  = (const float*)d_in[14];

    int N = in_sizes[0];
    int E = in_sizes[1] / 2;
    const int* src = ei;
    const int* dst = ei + E;

    const int TB = 256;
    int gN   = (N + TB - 1) / TB;
    int gN32 = (N * 32 + TB - 1) / TB;
    int e4   = (E + 3) / 4;
    int gE4  = (e4 + TB - 1) / TB;

    prep<<<gN, TB>>>(x, W1, as1, ad1, N);
    edge1<<<gE4, TB>>>(src, dst, E);
    node2<<<gN32, TB>>>(W1, b1, W2, as2, ad2, N);
    gat_l2<<<gN32, TB>>>(b2, W3, as3, ad3, N);
    edge3<<<gE4, TB>>>(src, dst, E);
    fin<<<gN, TB>>>(b3, (float*)d_out, N);
}

// round 12
// speedup vs baseline: 1.6061x; 1.6061x over previous
#include <cuda_runtime.h>
#include <cuda_fp16.h>

#define MAXN 50176
#define SLOT 128
#define LOG2E 1.4426950408889634f

// Scratch (__device__ globals; no allocation allowed)
__device__ __align__(256) __half2 g_h2h[MAXN * 32];  // layer-2 features fp16 packed
__device__ __align__(16) float2 g_sx1[MAXN];         // packed (s1, x)
__device__ __align__(16) float2 g_sh3[MAXN];         // packed (s3, h3)
__device__ float g_d1[MAXN];
__device__ float g_s2[MAXN], g_d2[MAXN];
__device__ float g_d3[MAXN];
__device__ int g_cursor[MAXN];       // INVARIANT: zero at entry (zero-init at load; gat_out resets)
__device__ int g_csr[MAXN * SLOT];   // fixed-stride CSR
// piecewise-linear table for h2(z) = A_m * z + C_m, 65 segments x 64 features
__device__ __align__(16) float g_tabA[65 * 64];
__device__ __align__(16) float g_tabC[65 * 64];
__device__ float g_knee[64];

__device__ __forceinline__ float leaky(float v) { return v > 0.f ? v : 0.2f * v; }

// ======= K1: node prep (rank-1 layer-1 scalars) + CSR scatter + (block 0) PWL table build =======
__global__ void prep_scatter(const float* __restrict__ x, const float* __restrict__ W1,
                             const float* __restrict__ as1, const float* __restrict__ ad1,
                             const float* __restrict__ b1, const float* __restrict__ W2,
                             const int* __restrict__ src, const int* __restrict__ dst,
                             int N, int E) {
    __shared__ float cs_sh, cd_sh;
    int base = blockIdx.x * blockDim.x;
    if (base < N && threadIdx.x == 0) {
        float cs = 0.f, cd = 0.f;
#pragma unroll
        for (int j = 0; j < 64; j++) { cs += W1[j] * as1[j]; cd += W1[j] * ad1[j]; }
        cs_sh = cs; cd_sh = cd;
    }
    if (base < N) __syncthreads();

    // ---- block 0: build the piecewise-linear (A,C) table ----
    if (blockIdx.x == 0) {
        __shared__ float rk[64], rw[64], rb[64];      // raw knee/w/b
        __shared__ float sk[64], sw[64], sb[64];      // sorted knee, sgn*w, sgn*b
        __shared__ int sidx[64];
        int t = threadIdx.x;
        if (t < 64) {
            float w = W1[t], b = b1[t];
            float knee = (w != 0.f) ? (-b / w) : __int_as_float(0x7f800000); // +inf
            rk[t] = knee; rw[t] = w; rb[t] = b;
        }
        __syncthreads();
        if (t < 64) {
            float knee = rk[t];
            int rank = 0;
            for (int j = 0; j < 64; j++)
                rank += (rk[j] < knee) || (rk[j] == knee && j < t);
            float w = rw[t], b = rb[t];
            float sgn = (w > 0.f) ? 1.f : ((w < 0.f) ? -1.f : 0.f);
            sk[rank] = knee;
            sw[rank] = sgn * w;
            sb[rank] = sgn * b;
            sidx[rank] = t;
        }
        __syncthreads();
        if (t < 64) {
            g_knee[t] = sk[t];
            // segment 0 (z below all knees): active = {w<0} U {w==0 && b>0}
            float A = 0.f, C = 0.f;
            for (int j = 0; j < 64; j++) {
                float w = rw[j], b = rb[j];
                bool act = (w < 0.f) || (w == 0.f && b > 0.f);
                if (act) {
                    float w2v = W2[j * 64 + t];
                    A += w * w2v;
                    C += b * w2v;
                }
            }
            g_tabA[t] = A;
            g_tabC[t] = C;
            for (int m = 1; m <= 64; m++) {
                int j = sidx[m - 1];
                float w2v = W2[j * 64 + t];
                A += sw[m - 1] * w2v;
                C += sb[m - 1] * w2v;
                g_tabA[m * 64 + t] = A;
                g_tabC[m * 64 + t] = C;
            }
        }
    }

    // ---- edge work: 4 edges/thread, cursor-ATOMG CSR scatter ----
    int t = base + threadIdx.x;
    int e0 = t * 4;
    if (e0 + 3 < E) {
        int4 s4 = ((const int4*)src)[t];
        int4 d4 = ((const int4*)dst)[t];
        int r0 = atomicAdd(&g_cursor[d4.x], 1);
        int r1 = atomicAdd(&g_cursor[d4.y], 1);
        int r2 = atomicAdd(&g_cursor[d4.z], 1);
        int r3 = atomicAdd(&g_cursor[d4.w], 1);
        g_csr[d4.x * SLOT + r0] = s4.x;
        g_csr[d4.y * SLOT + r1] = s4.y;
        g_csr[d4.z * SLOT + r2] = s4.z;
        g_csr[d4.w * SLOT + r3] = s4.w;
    } else if (e0 < E) {
        for (int e = e0; e < E; e++) {
            int d = dst[e];
            int r = atomicAdd(&g_cursor[d], 1);
            g_csr[d * SLOT + r] = src[e];
        }
    }
    if (t < N) {
        float xv = x[t];
        g_sx1[t] = make_float2(xv * cs_sh, xv);
        g_d1[t] = xv * cd_sh;
    }
}

// ======= K2: layer-1 scalar GAT + table-based layer-2 transform =======
__global__ void gat_l1_fused(const float* __restrict__ as2, const float* __restrict__ ad2, int N) {
    int node = (blockIdx.x * blockDim.x + threadIdx.x) >> 5;
    int lane = threadIdx.x & 31;
    if (node >= N) return;
    int off = node * SLOT;
    int deg = g_cursor[node];
    float dn = g_d1[node];
    float2 self = g_sx1[node];

    float dsum = 0.f, zacc = 0.f;
    for (int j = lane; j < deg; j += 32) {
        int sv = g_csr[off + j];
        float2 t = g_sx1[sv];
        float ex = exp2f(leaky(t.x + dn) * LOG2E);
        dsum += ex;
        zacc += ex * t.y;
    }
#pragma unroll
    for (int o = 16; o; o >>= 1) {
        dsum += __shfl_xor_sync(0xffffffffu, dsum, o);
        zacc += __shfl_xor_sync(0xffffffffu, zacc, o);
    }
    float exs = exp2f(leaky(self.x + dn) * LOG2E);
    float z = (zacc + exs * self.y) / (dsum + exs);

    // piecewise-linear segment: m = #knees < z. Search range [0,64] (s starts at 64!)
    int m = 0;
#pragma unroll
    for (int s = 64; s; s >>= 1) {
        int t = m + s;
        if (t <= 64 && g_knee[t - 1] < z) m = t;
    }
    float2 A = ((const float2*)g_tabA)[m * 32 + lane];
    float2 C = ((const float2*)g_tabC)[m * 32 + lane];
    float o0 = A.x * z + C.x;
    float o1 = A.y * z + C.y;

    g_h2h[node * 32 + lane] = __floats2half2_rn(o0, o1);
    float2 a_s = ((const float2*)as2)[lane];
    float2 a_d = ((const float2*)ad2)[lane];
    float ps = o0 * a_s.x + o1 * a_s.y;
    float pd = o0 * a_d.x + o1 * a_d.y;
#pragma unroll
    for (int o = 16; o; o >>= 1) {
        ps += __shfl_down_sync(0xffffffffu, ps, o);
        pd += __shfl_down_sync(0xffffffffu, pd, o);
    }
    if (lane == 0) { g_s2[node] = ps; g_d2[node] = pd; }
}

// ======= K3: layer-2 wide GAT (fp16 gather) + layer-3 projection =======
__global__ void gat_l2(const float* __restrict__ b2, const float* __restrict__ W3,
                       const float* __restrict__ as3, const float* __restrict__ ad3, int N) {
    int node = (blockIdx.x * blockDim.x + threadIdx.x) >> 5;
    int lane = threadIdx.x & 31;
    if (node >= N) return;
    int off = node * SLOT;
    int deg = g_cursor[node];
    float dn = g_d2[node];

    float exs = exp2f(leaky(g_s2[node] + dn) * LOG2E);
    float2 hself = __half22float2(g_h2h[node * 32 + lane]);
    float a0 = exs * hself.x;
    float a1 = exs * hself.y;
    float dsum = 0.f;
    for (int r = 0; r < deg; r += 32) {
        int j = r + lane;
        int sv = 0;
        float exv = 0.f;
        if (j < deg) {
            sv = g_csr[off + j];
            exv = exp2f(leaky(g_s2[sv] + dn) * LOG2E);
        }
        dsum += exv;
        int cnt = min(32, deg - r);
        if (cnt == 32) {
#pragma unroll 8
            for (int k = 0; k < 32; k++) {
                int sj = __shfl_sync(0xffffffffu, sv, k);
                float exj = __shfl_sync(0xffffffffu, exv, k);
                float2 hv = __half22float2(g_h2h[sj * 32 + lane]);
                a0 += exj * hv.x;
                a1 += exj * hv.y;
            }
        } else {
            for (int k = 0; k < cnt; k++) {
                int sj = __shfl_sync(0xffffffffu, sv, k);
                float exj = __shfl_sync(0xffffffffu, exv, k);
                float2 hv = __half22float2(g_h2h[sj * 32 + lane]);
                a0 += exj * hv.x;
                a1 += exj * hv.y;
            }
        }
    }
#pragma unroll
    for (int o = 16; o; o >>= 1) dsum += __shfl_xor_sync(0xffffffffu, dsum, o);
    float inv = 1.f / (exs + dsum);
    float2 bb = ((const float2*)b2)[lane];
    float2 w3 = ((const float2*)W3)[lane];
    float x30 = fmaxf(a0 * inv + bb.x, 0.f);
    float x31 = fmaxf(a1 * inv + bb.y, 0.f);
    float p = x30 * w3.x + x31 * w3.y;
#pragma unroll
    for (int o = 16; o; o >>= 1) p += __shfl_down_sync(0xffffffffu, p, o);
    if (lane == 0) {
        g_sh3[node] = make_float2(p * as3[0], p);
        g_d3[node] = p * ad3[0];
    }
}

// ======= K4: layer-3 scalar GAT -> output; resets cursor invariant =======
__global__ void gat_out(const float* __restrict__ b3, float* __restrict__ out, int N) {
    int node = (blockIdx.x * blockDim.x + threadIdx.x) >> 5;
    int lane = threadIdx.x & 31;
    if (node >= N) return;
    int off = node * SLOT;
    int deg = g_cursor[node];
    float dn = g_d3[node];
    float2 self = g_sh3[node];

    float dsum = 0.f, acc = 0.f;
    for (int j = lane; j < deg; j += 32) {
        int sv = g_csr[off + j];
        float2 t = g_sh3[sv];
        float ex = exp2f(leaky(t.x + dn) * LOG2E);
        dsum += ex;
        acc += ex * t.y;
    }
#pragma unroll
    for (int o = 16; o; o >>= 1) {
        dsum += __shfl_xor_sync(0xffffffffu, dsum, o);
        acc += __shfl_xor_sync(0xffffffffu, acc, o);
    }
    if (lane == 0) {
        float exs = exp2f(leaky(self.x + dn) * LOG2E);
        out[node] = (acc + exs * self.y) / (dsum + exs) + b3[0];
        g_cursor[node] = 0;   // restore invariant for next call
    }
}

extern "C" void kernel_launch(void* const* d_in, const int* in_sizes, int n_in,
                              void* d_out, int out_size) {
    const float* x   = (const float*)d_in[0];
    const int*   ei  = (const int*)d_in[1];
    const float* W1  = (const float*)d_in[3];
    const float* as1 = (const float*)d_in[4];
    const float* ad1 = (const float*)d_in[5];
    const float* b1  = (const float*)d_in[6];
    const float* W2  = (const float*)d_in[7];
    const float* as2 = (const float*)d_in[8];
    const float* ad2 = (const float*)d_in[9];
    const float* b2  = (const float*)d_in[10];
    const float* W3  = (const float*)d_in[11];
    const float* as3 = (const float*)d_in[12];
    const float* ad3 = (const float*)d_in[13];
    const float* b3  = (const float*)d_in[14];

    int N = in_sizes[0];
    int E = in_sizes[1] / 2;
    const int* src = ei;
    const int* dst = ei + E;

    const int TB = 256;
    int gN32 = (N * 32 + TB - 1) / TB;
    int e4   = (E + 3) / 4;
    int gPS  = (((e4 > N) ? e4 : N) + TB - 1) / TB;

    prep_scatter<<<gPS, TB>>>(x, W1, as1, ad1, b1, W2, src, dst, N, E);
    gat_l1_fused<<<gN32, TB>>>(as2, ad2, N);
    gat_l2<<<gN32, TB>>>(b2, W3, as3, ad3, N);
    gat_out<<<gN32, TB>>>(b3, (float*)d_out, N);
}